// round 13
// baseline (speedup 1.0000x reference)
#include <cuda_runtime.h>
#include <cuda_fp16.h>

// Trilinear resample, zero boundary.
// inputs:      [B=2, X=144, Y=144, Z=144, C=2] fp32
// deformation: [B, X, Y, Z, 3] fp32 absolute voxel coords
// output:      [B, X, Y, Z, C] fp32
//
// Per-batch table (47.8 MB each, double-buffered): T[x][y][z] = 8 fp16 =
// 2x2 (y,z) corner block, 2 ch, zero-padded at y/z upper edges. Schedule
// (fork-join, graph-capturable): expand(b0) -> [main(b0) || expand(b1)] ->
// main(b1). evict_last on table, def/out stream. Main: 2 voxels/thread,
// two aligned 16B gathers per voxel.

#define SX 144
#define SY 144
#define SZ 144
#define NC 2
#define NB 2
#define VOL (SX * SY * SZ)

__device__ uint4 g_exp0[(size_t)VOL];
__device__ uint4 g_exp1[(size_t)VOL];

// Side stream + fork/join events, created once at process start (no device
// memory involved; kernel_launch does identical work every call).
static cudaStream_t g_s2;
static cudaEvent_t g_evFork, g_evJoin;
namespace {
struct StreamInit {
    StreamInit() {
        cudaStreamCreateWithFlags(&g_s2, cudaStreamNonBlocking);
        cudaEventCreateWithFlags(&g_evFork, cudaEventDisableTiming);
        cudaEventCreateWithFlags(&g_evJoin, cudaEventDisableTiming);
    }
};
StreamInit g_stream_init;
}

static __device__ __forceinline__ unsigned pack_h2(float a, float b) {
    __half2 h = __floats2half2_rn(a, b);
    return *(unsigned*)&h;
}
static __device__ __forceinline__ float2 unpack_h2(unsigned u) {
    __half2 h = *(__half2*)&u;
    return __half22float2(h);
}

static __device__ __forceinline__ unsigned long long evict_last_policy() {
    unsigned long long pol;
    asm("createpolicy.fractional.L2::evict_last.b64 %0, 1.0;" : "=l"(pol));
    return pol;
}
static __device__ __forceinline__ void st_evict_last(
    uint4* p, uint4 v, unsigned long long pol) {
    asm volatile("st.global.L2::cache_hint.v4.b32 [%0], {%1,%2,%3,%4}, %5;"
                 :: "l"(p), "r"(v.x), "r"(v.y), "r"(v.z), "r"(v.w), "l"(pol)
                 : "memory");
}
static __device__ __forceinline__ uint4 ld_evict_last(
    const uint4* p, unsigned long long pol) {
    uint4 v;
    asm("ld.global.nc.L2::cache_hint.v4.b32 {%0,%1,%2,%3}, [%4], %5;"
        : "=r"(v.x), "=r"(v.y), "=r"(v.z), "=r"(v.w) : "l"(p), "l"(pol));
    return v;
}

// Prep for one batch into the given table.
__global__ __launch_bounds__(256) void expand_kernel(
    const float* __restrict__ inpb, uint4* __restrict__ tab, int n)  // n = VOL
{
    int idx = blockIdx.x * blockDim.x + threadIdx.x;
    if (idx >= n) return;

    int z = idx % SZ;
    int r = idx / SZ;
    int y = r % SY;

    const float* p00 = inpb + (size_t)idx * NC;  // (y, z)
    bool zv = (z + 1 < SZ);
    bool yv = (y + 1 < SY);

    float2 v00 = *(const float2*)p00;
    float2 v01 = zv ? *(const float2*)(p00 + NC) : make_float2(0.f, 0.f);
    float2 v10 = yv ? *(const float2*)(p00 + SZ * NC) : make_float2(0.f, 0.f);
    float2 v11 = (yv && zv) ? *(const float2*)(p00 + (SZ + 1) * NC)
                            : make_float2(0.f, 0.f);

    uint4 o;
    o.x = pack_h2(v00.x, v00.y);
    o.y = pack_h2(v01.x, v01.y);
    o.z = pack_h2(v10.x, v10.y);
    o.w = pack_h2(v11.x, v11.y);
    st_evict_last(&tab[idx], o, evict_last_policy());
}

// Per-voxel interpolation: two 16B gathers (x0 and x1 rows).
static __device__ __forceinline__ float2 interp_one(
    const uint4* __restrict__ tab,
    float cx, float cy, float cz, unsigned long long pol)
{
    float fx = floorf(cx), fy = floorf(cy), fz = floorf(cz);
    int ix0 = (int)fx, iy0 = (int)fy, iz0 = (int)fz;
    float tx = cx - fx, ty = cy - fy, tz = cz - fz;

    float wy0 = 1.0f - ty, wy1 = ty;
    float wz0 = 1.0f - tz, wz1 = tz;
    float w00 = wy0 * wz0, w01 = wy0 * wz1;
    float w10 = wy1 * wz0, w11 = wy1 * wz1;

    bool vyz = (iy0 >= 0) & (iy0 < SY) & (iz0 >= 0) & (iz0 < SZ);
    unsigned cyp = (unsigned)min(max(iy0, 0), SY - 1);
    unsigned czp = (unsigned)min(max(iz0, 0), SZ - 1);

    bool vx0 = (ix0 >= 0) & (ix0 < SX);
    bool vx1 = (ix0 + 1 >= 0) & (ix0 + 1 < SX);
    unsigned cx0 = (unsigned)min(max(ix0, 0), SX - 1);
    unsigned cx1 = (unsigned)min(max(ix0 + 1, 0), SX - 1);

    unsigned base = cyp * SZ + czp;
    uint4 oA = ld_evict_last(&tab[base + cx0 * (unsigned)(SY * SZ)], pol);
    uint4 oB = ld_evict_last(&tab[base + cx1 * (unsigned)(SY * SZ)], pol);

    float wxv0 = (vx0 & vyz) ? (1.0f - tx) : 0.0f;
    float wxv1 = (vx1 & vyz) ? tx : 0.0f;

    float2 a00 = unpack_h2(oA.x), a01 = unpack_h2(oA.y);
    float2 a10 = unpack_h2(oA.z), a11 = unpack_h2(oA.w);
    float2 b00 = unpack_h2(oB.x), b01 = unpack_h2(oB.y);
    float2 b10 = unpack_h2(oB.z), b11 = unpack_h2(oB.w);

    float sA0 = w00 * a00.x + w01 * a01.x + w10 * a10.x + w11 * a11.x;
    float sA1 = w00 * a00.y + w01 * a01.y + w10 * a10.y + w11 * a11.y;
    float sB0 = w00 * b00.x + w01 * b01.x + w10 * b10.x + w11 * b11.x;
    float sB1 = w00 * b00.y + w01 * b01.y + w10 * b10.y + w11 * b11.y;

    return make_float2(wxv0 * sA0 + wxv1 * sB0,
                       wxv0 * sA1 + wxv1 * sB1);
}

__global__ __launch_bounds__(256) void resample_main2(
    const float* __restrict__ defb,
    float* __restrict__ outb,
    const uint4* __restrict__ tab,
    int npairs)  // VOL/2
{
    int t = blockIdx.x * blockDim.x + threadIdx.x;
    if (t >= npairs) return;

    unsigned long long pol = evict_last_policy();

    const float2* dp = (const float2*)(defb + (size_t)(2 * t) * 3);
    float2 d0 = __ldcs(dp + 0);  // cx0, cy0
    float2 d1 = __ldcs(dp + 1);  // cz0, cx1
    float2 d2 = __ldcs(dp + 2);  // cy1, cz1

    float2 r0 = interp_one(tab, d0.x, d0.y, d1.x, pol);
    float2 r1 = interp_one(tab, d1.y, d2.x, d2.y, pol);

    __stcs((float4*)outb + t, make_float4(r0.x, r0.y, r1.x, r1.y));
}

// Exact fallback (R2 kernel) in case sizes differ from the expected shape.
__global__ __launch_bounds__(256) void resample_fallback(
    const float* __restrict__ inp,
    const float* __restrict__ def,
    float* __restrict__ out,
    int total)
{
    int idx = blockIdx.x * blockDim.x + threadIdx.x;
    if (idx >= total) return;
    int b = idx / VOL;
    const float* d = def + (size_t)idx * 3;
    float cx = __ldg(d + 0), cy = __ldg(d + 1), cz = __ldg(d + 2);
    float fx = floorf(cx), fy = floorf(cy), fz = floorf(cz);
    int ix0 = (int)fx, iy0 = (int)fy, iz0 = (int)fz;
    float tx = cx - fx, ty = cy - fy, tz = cz - fz;
    float wxw[2] = {1.0f - tx, tx};
    float wyw[2] = {1.0f - ty, ty};
    float wzw[2] = {1.0f - tz, tz};
    const float* base = inp + (size_t)b * VOL * NC;
    float acc0 = 0.f, acc1 = 0.f;
#pragma unroll
    for (int dx = 0; dx < 2; dx++) {
        int ix = ix0 + dx;
        bool vx = (ix >= 0) & (ix < SX);
        int cxp = min(max(ix, 0), SX - 1);
#pragma unroll
        for (int dy = 0; dy < 2; dy++) {
            int iy = iy0 + dy;
            bool vxy = vx & (iy >= 0) & (iy < SY);
            int cyp = min(max(iy, 0), SY - 1);
            float wxy = wxw[dx] * wyw[dy];
            const float* row = base + ((size_t)cxp * SY + cyp) * SZ * NC;
#pragma unroll
            for (int dz = 0; dz < 2; dz++) {
                int iz = iz0 + dz;
                bool v = vxy & (iz >= 0) & (iz < SZ);
                int czp = min(max(iz, 0), SZ - 1);
                float2 val = __ldg((const float2*)(row + (size_t)czp * NC));
                float w = v ? (wxy * wzw[dz]) : 0.0f;
                acc0 = fmaf(w, val.x, acc0);
                acc1 = fmaf(w, val.y, acc1);
            }
        }
    }
    ((float2*)out)[idx] = make_float2(acc0, acc1);
}

extern "C" void kernel_launch(void* const* d_in, const int* in_sizes, int n_in,
                              void* d_out, int out_size)
{
    int total = out_size / NC;

    const float* inp = (const float*)d_in[0];
    const float* def = (const float*)d_in[1];
    if (n_in >= 2) {
        long long t = (long long)total;
        if ((long long)in_sizes[0] == 3LL * t && (long long)in_sizes[1] == 2LL * t) {
            def = (const float*)d_in[0];
            inp = (const float*)d_in[1];
        }
    }

    const int threads = 256;

    if (total == NB * VOL) {
        int blocksE = (VOL + threads - 1) / threads;
        int npairs = VOL / 2;
        int blocksM = (npairs + threads - 1) / threads;

        uint4* tab0;  cudaGetSymbolAddress((void**)&tab0, g_exp0);
        uint4* tab1;  cudaGetSymbolAddress((void**)&tab1, g_exp1);

        // expand(b0) on the main (null) stream.
        expand_kernel<<<blocksE, threads>>>(inp, tab0, VOL);

        // Fork: expand(b1) on side stream, concurrent with main(b0).
        cudaEventRecord(g_evFork, 0);
        cudaStreamWaitEvent(g_s2, g_evFork, 0);
        expand_kernel<<<blocksE, threads, 0, g_s2>>>(
            inp + (size_t)VOL * NC, tab1, VOL);
        cudaEventRecord(g_evJoin, g_s2);

        // main(b0) on the main stream (overlaps expand(b1)).
        resample_main2<<<blocksM, threads>>>(
            def, (float*)d_out, tab0, npairs);

        // Join, then main(b1).
        cudaStreamWaitEvent(0, g_evJoin, 0);
        resample_main2<<<blocksM, threads>>>(
            def + (size_t)VOL * 3,
            (float*)d_out + (size_t)VOL * NC,
            tab1, npairs);
    } else {
        int blocks = (total + threads - 1) / threads;
        resample_fallback<<<blocks, threads>>>(inp, def, (float*)d_out, total);
    }
}

// round 14
// speedup vs baseline: 1.0424x; 1.0424x over previous
#include <cuda_runtime.h>
#include <cuda_fp16.h>

// Trilinear resample, zero boundary.
// inputs:      [B=2, X=144, Y=144, Z=144, C=2] fp32
// deformation: [B, X, Y, Z, 3] fp32 absolute voxel coords
// output:      [B, X, Y, Z, C] fp32
//
// Per-batch table (47.8 MB each, double-buffered): T[x][y][z] = 8 fp16 =
// 2x2 (y,z) corner block, 2 ch, zero-padded at y/z upper edges.
// Schedule (single stream): expand(b0) -> fused[main(b0) || expand(b1)]
// -> main(b1). Fusion = grid role split by blockIdx parity (no streams,
// no events, graph-capturable). evict_last on table, def/out stream.

#define SX 144
#define SY 144
#define SZ 144
#define NC 2
#define NB 2
#define VOL (SX * SY * SZ)
#define NPAIRS (VOL / 2)          // 1492992 = 5832 * 256
#define BLOCKS_HALF (NPAIRS / 256) // 5832

__device__ uint4 g_exp0[(size_t)VOL];
__device__ uint4 g_exp1[(size_t)VOL];

static __device__ __forceinline__ unsigned pack_h2(float a, float b) {
    __half2 h = __floats2half2_rn(a, b);
    return *(unsigned*)&h;
}
static __device__ __forceinline__ float2 unpack_h2(unsigned u) {
    __half2 h = *(__half2*)&u;
    return __half22float2(h);
}

static __device__ __forceinline__ unsigned long long evict_last_policy() {
    unsigned long long pol;
    asm("createpolicy.fractional.L2::evict_last.b64 %0, 1.0;" : "=l"(pol));
    return pol;
}
static __device__ __forceinline__ void st_evict_last(
    uint4* p, uint4 v, unsigned long long pol) {
    asm volatile("st.global.L2::cache_hint.v4.b32 [%0], {%1,%2,%3,%4}, %5;"
                 :: "l"(p), "r"(v.x), "r"(v.y), "r"(v.z), "r"(v.w), "l"(pol)
                 : "memory");
}
static __device__ __forceinline__ uint4 ld_evict_last(
    const uint4* p, unsigned long long pol) {
    uint4 v;
    asm("ld.global.nc.L2::cache_hint.v4.b32 {%0,%1,%2,%3}, [%4], %5;"
        : "=r"(v.x), "=r"(v.y), "=r"(v.z), "=r"(v.w) : "l"(p), "l"(pol));
    return v;
}

// Build one table entry (batch-local idx = x*SY*SZ + y*SZ + z).
static __device__ __forceinline__ void expand_entry(
    const float* __restrict__ inpb, uint4* __restrict__ tab, int idx,
    unsigned long long pol)
{
    int z = idx % SZ;
    int r = idx / SZ;
    int y = r % SY;

    const float* p00 = inpb + (size_t)idx * NC;  // (y, z)
    bool zv = (z + 1 < SZ);
    bool yv = (y + 1 < SY);

    float2 v00 = *(const float2*)p00;
    float2 v01 = zv ? *(const float2*)(p00 + NC) : make_float2(0.f, 0.f);
    float2 v10 = yv ? *(const float2*)(p00 + SZ * NC) : make_float2(0.f, 0.f);
    float2 v11 = (yv && zv) ? *(const float2*)(p00 + (SZ + 1) * NC)
                            : make_float2(0.f, 0.f);

    uint4 o;
    o.x = pack_h2(v00.x, v00.y);
    o.y = pack_h2(v01.x, v01.y);
    o.z = pack_h2(v10.x, v10.y);
    o.w = pack_h2(v11.x, v11.y);
    st_evict_last(&tab[idx], o, pol);
}

// Per-voxel interpolation: two 16B gathers (x0 and x1 rows).
static __device__ __forceinline__ float2 interp_one(
    const uint4* __restrict__ tab,
    float cx, float cy, float cz, unsigned long long pol)
{
    float fx = floorf(cx), fy = floorf(cy), fz = floorf(cz);
    int ix0 = (int)fx, iy0 = (int)fy, iz0 = (int)fz;
    float tx = cx - fx, ty = cy - fy, tz = cz - fz;

    float wy0 = 1.0f - ty, wy1 = ty;
    float wz0 = 1.0f - tz, wz1 = tz;
    float w00 = wy0 * wz0, w01 = wy0 * wz1;
    float w10 = wy1 * wz0, w11 = wy1 * wz1;

    bool vyz = (iy0 >= 0) & (iy0 < SY) & (iz0 >= 0) & (iz0 < SZ);
    unsigned cyp = (unsigned)min(max(iy0, 0), SY - 1);
    unsigned czp = (unsigned)min(max(iz0, 0), SZ - 1);

    bool vx0 = (ix0 >= 0) & (ix0 < SX);
    bool vx1 = (ix0 + 1 >= 0) & (ix0 + 1 < SX);
    unsigned cx0 = (unsigned)min(max(ix0, 0), SX - 1);
    unsigned cx1 = (unsigned)min(max(ix0 + 1, 0), SX - 1);

    unsigned base = cyp * SZ + czp;
    uint4 oA = ld_evict_last(&tab[base + cx0 * (unsigned)(SY * SZ)], pol);
    uint4 oB = ld_evict_last(&tab[base + cx1 * (unsigned)(SY * SZ)], pol);

    float wxv0 = (vx0 & vyz) ? (1.0f - tx) : 0.0f;
    float wxv1 = (vx1 & vyz) ? tx : 0.0f;

    float2 a00 = unpack_h2(oA.x), a01 = unpack_h2(oA.y);
    float2 a10 = unpack_h2(oA.z), a11 = unpack_h2(oA.w);
    float2 b00 = unpack_h2(oB.x), b01 = unpack_h2(oB.y);
    float2 b10 = unpack_h2(oB.z), b11 = unpack_h2(oB.w);

    float sA0 = w00 * a00.x + w01 * a01.x + w10 * a10.x + w11 * a11.x;
    float sA1 = w00 * a00.y + w01 * a01.y + w10 * a10.y + w11 * a11.y;
    float sB0 = w00 * b00.x + w01 * b01.x + w10 * b10.x + w11 * b11.x;
    float sB1 = w00 * b00.y + w01 * b01.y + w10 * b10.y + w11 * b11.y;

    return make_float2(wxv0 * sA0 + wxv1 * sB0,
                       wxv0 * sA1 + wxv1 * sB1);
}

// Process one voxel pair (pair index t) of a batch.
static __device__ __forceinline__ void main_pair(
    const float* __restrict__ defb, float* __restrict__ outb,
    const uint4* __restrict__ tab, int t, unsigned long long pol)
{
    const float2* dp = (const float2*)(defb + (size_t)(2 * t) * 3);
    float2 d0 = __ldcs(dp + 0);  // cx0, cy0
    float2 d1 = __ldcs(dp + 1);  // cz0, cx1
    float2 d2 = __ldcs(dp + 2);  // cy1, cz1

    float2 r0 = interp_one(tab, d0.x, d0.y, d1.x, pol);
    float2 r1 = interp_one(tab, d1.y, d2.x, d2.y, pol);

    __stcs((float4*)outb + t, make_float4(r0.x, r0.y, r1.x, r1.y));
}

// Standalone expand for batch 0 (1 entry/thread).
__global__ __launch_bounds__(256) void expand_kernel(
    const float* __restrict__ inpb, uint4* __restrict__ tab, int n)
{
    int idx = blockIdx.x * blockDim.x + threadIdx.x;
    if (idx >= n) return;
    expand_entry(inpb, tab, idx, evict_last_policy());
}

// Standalone main for batch 1.
__global__ __launch_bounds__(256) void resample_main2(
    const float* __restrict__ defb,
    float* __restrict__ outb,
    const uint4* __restrict__ tab,
    int npairs)
{
    int t = blockIdx.x * blockDim.x + threadIdx.x;
    if (t >= npairs) return;
    main_pair(defb, outb, tab, t, evict_last_policy());
}

// Fused: even blocks -> main(b0); odd blocks -> expand(b1), 2 entries/thread.
// Grid = 2 * BLOCKS_HALF.
__global__ __launch_bounds__(256) void fused_main0_expand1(
    const float* __restrict__ def0, float* __restrict__ out0,
    const uint4* __restrict__ tab0,
    const float* __restrict__ inp1, uint4* __restrict__ tab1)
{
    unsigned long long pol = evict_last_policy();
    int half = blockIdx.x >> 1;
    if ((blockIdx.x & 1) == 0) {
        // main(b0): pair index
        int t = half * 256 + threadIdx.x;
        main_pair(def0, out0, tab0, t, pol);
    } else {
        // expand(b1): 2 consecutive entries per thread
        int e = (half * 256 + threadIdx.x) * 2;
        expand_entry(inp1, tab1, e, pol);
        expand_entry(inp1, tab1, e + 1, pol);
    }
}

// Exact fallback (R2 kernel) in case sizes differ from the expected shape.
__global__ __launch_bounds__(256) void resample_fallback(
    const float* __restrict__ inp,
    const float* __restrict__ def,
    float* __restrict__ out,
    int total)
{
    int idx = blockIdx.x * blockDim.x + threadIdx.x;
    if (idx >= total) return;
    int b = idx / VOL;
    const float* d = def + (size_t)idx * 3;
    float cx = __ldg(d + 0), cy = __ldg(d + 1), cz = __ldg(d + 2);
    float fx = floorf(cx), fy = floorf(cy), fz = floorf(cz);
    int ix0 = (int)fx, iy0 = (int)fy, iz0 = (int)fz;
    float tx = cx - fx, ty = cy - fy, tz = cz - fz;
    float wxw[2] = {1.0f - tx, tx};
    float wyw[2] = {1.0f - ty, ty};
    float wzw[2] = {1.0f - tz, tz};
    const float* base = inp + (size_t)b * VOL * NC;
    float acc0 = 0.f, acc1 = 0.f;
#pragma unroll
    for (int dx = 0; dx < 2; dx++) {
        int ix = ix0 + dx;
        bool vx = (ix >= 0) & (ix < SX);
        int cxp = min(max(ix, 0), SX - 1);
#pragma unroll
        for (int dy = 0; dy < 2; dy++) {
            int iy = iy0 + dy;
            bool vxy = vx & (iy >= 0) & (iy < SY);
            int cyp = min(max(iy, 0), SY - 1);
            float wxy = wxw[dx] * wyw[dy];
            const float* row = base + ((size_t)cxp * SY + cyp) * SZ * NC;
#pragma unroll
            for (int dz = 0; dz < 2; dz++) {
                int iz = iz0 + dz;
                bool v = vxy & (iz >= 0) & (iz < SZ);
                int czp = min(max(iz, 0), SZ - 1);
                float2 val = __ldg((const float2*)(row + (size_t)czp * NC));
                float w = v ? (wxy * wzw[dz]) : 0.0f;
                acc0 = fmaf(w, val.x, acc0);
                acc1 = fmaf(w, val.y, acc1);
            }
        }
    }
    ((float2*)out)[idx] = make_float2(acc0, acc1);
}

extern "C" void kernel_launch(void* const* d_in, const int* in_sizes, int n_in,
                              void* d_out, int out_size)
{
    int total = out_size / NC;

    const float* inp = (const float*)d_in[0];
    const float* def = (const float*)d_in[1];
    if (n_in >= 2) {
        long long t = (long long)total;
        if ((long long)in_sizes[0] == 3LL * t && (long long)in_sizes[1] == 2LL * t) {
            def = (const float*)d_in[0];
            inp = (const float*)d_in[1];
        }
    }

    const int threads = 256;

    if (total == NB * VOL) {
        uint4* tab0;  cudaGetSymbolAddress((void**)&tab0, g_exp0);
        uint4* tab1;  cudaGetSymbolAddress((void**)&tab1, g_exp1);

        int blocksE = (VOL + threads - 1) / threads;

        // 1. expand(b0)
        expand_kernel<<<blocksE, threads>>>(inp, tab0, VOL);

        // 2. fused: main(b0) || expand(b1)
        fused_main0_expand1<<<2 * BLOCKS_HALF, threads>>>(
            def, (float*)d_out, tab0,
            inp + (size_t)VOL * NC, tab1);

        // 3. main(b1)
        resample_main2<<<BLOCKS_HALF, threads>>>(
            def + (size_t)VOL * 3,
            (float*)d_out + (size_t)VOL * NC,
            tab1, NPAIRS);
    } else {
        int blocks = (total + threads - 1) / threads;
        resample_fallback<<<blocks, threads>>>(inp, def, (float*)d_out, total);
    }
}